// round 11
// baseline (speedup 1.0000x reference)
#include <cuda_runtime.h>
#include <cuda_bf16.h>
#include <cstdint>

#define NB    4
#define NSEQ  4096
#define DIM   512
#define BQ    64
#define BK    64
#define NKT   (NSEQ/BK)
#define NTHR  512
#define THRESH 70.0f

// bf16 copy of X (no cudaMalloc allowed -> device global scratch)
__device__ __nv_bfloat16 g_Xb[(size_t)NB*NSEQ*DIM];

// dynamic smem (bytes). Tile rows are 512 bf16 = 1024B, swizzled in 16B chunks.
#define SM_Q     0
#define SM_K(i)  (65536 + (i)*65536)
#define SM_RED   196608                 // 3 wd-sources x 4 quads x 2KB (bf16x2 partials)
#define SM_CAND  221184                 // float2[64][16] = 8KB
#define SMEM_BYTES (221184 + 8192)      // 229376

// ---------------- PTX helpers (plain-sm_103 legal) ----------------
__device__ __forceinline__ uint32_t smem_u32(const void* p) {
    uint32_t a;
    asm("{ .reg .u64 t; cvta.to.shared.u64 t, %1; cvt.u32.u64 %0, t; }" : "=r"(a) : "l"(p));
    return a;
}
#define CP16(dst, src) \
    asm volatile("cp.async.cg.shared.global [%0], [%1], 16;" \
        :: "r"((uint32_t)(dst)), "l"((unsigned long long)__cvta_generic_to_global((const void*)(src))) : "memory")
#define CP_COMMIT()  asm volatile("cp.async.commit_group;" ::: "memory")
#define CP_WAIT(n)   asm volatile("cp.async.wait_group %0;" :: "n"(n) : "memory")

__device__ __forceinline__ void ldsm4(uint32_t* r, uint32_t a) {
    asm volatile("ldmatrix.sync.aligned.m8n8.x4.shared.b16 {%0,%1,%2,%3}, [%4];"
        : "=r"(r[0]), "=r"(r[1]), "=r"(r[2]), "=r"(r[3]) : "r"(a));
}
__device__ __forceinline__ void mma16816(float* c, const uint32_t* a, const uint32_t* b) {
    asm volatile("mma.sync.aligned.m16n8k16.row.col.f32.bf16.bf16.f32 "
        "{%0,%1,%2,%3}, {%4,%5,%6,%7}, {%8,%9}, {%0,%1,%2,%3};"
        : "+f"(c[0]), "+f"(c[1]), "+f"(c[2]), "+f"(c[3])
        : "r"(a[0]), "r"(a[1]), "r"(a[2]), "r"(a[3]), "r"(b[0]), "r"(b[1]));
}
// in-row 16B-chunk swizzle: chunk c of row r lives at chunk ((c&~7)|((c^r)&7))
__device__ __forceinline__ int swz(int c, int r) { return (c & ~7) | ((c ^ r) & 7); }

// bf16x2 pack/unpack via ushort bit-casts (portable across cuda_bf16.h versions)
__device__ __forceinline__ uint32_t pack_bf16x2(float lo, float hi) {
    __nv_bfloat162 h = __floats2bfloat162_rn(lo, hi);
    return (uint32_t)__bfloat16_as_ushort(h.x) | ((uint32_t)__bfloat16_as_ushort(h.y) << 16);
}
__device__ __forceinline__ float2 unpack_bf16x2(uint32_t v) {
    __nv_bfloat16 lo = __ushort_as_bfloat16((unsigned short)(v & 0xffffu));
    __nv_bfloat16 hi = __ushort_as_bfloat16((unsigned short)(v >> 16));
    return make_float2(__bfloat162float(lo), __bfloat162float(hi));
}

__device__ __forceinline__ void ins2(float v, int idx, float& t1, int& i1, float& t2, int& i2) {
    if (v > t2) {
        if (v > t1) { t2 = t1; i2 = i1; t1 = v; i1 = idx; }
        else        { t2 = v;  i2 = idx; }
    }
}

// load a 64x512 bf16 tile (row-major, rows 1024B) into swizzled smem via cp.async
__device__ __forceinline__ void load_tile(uint32_t sbase, const __nv_bfloat16* src, int tid) {
#pragma unroll
    for (int i = 0; i < 8; ++i) {
        int c   = tid + i * NTHR;       // 4096 16B-chunks
        int row = c >> 6, ch = c & 63;
        CP16(sbase + row * 1024 + swz(ch, row) * 16, src + (size_t)row * DIM + ch * 8);
    }
    CP_COMMIT();
}

extern "C" __global__ void cvt_kernel(const float* __restrict__ X) {
    size_t i = (size_t)blockIdx.x * 256 + threadIdx.x;   // one float4 each
    float4 v = ((const float4*)X)[i];
    __nv_bfloat162* o = (__nv_bfloat162*)g_Xb;
    o[i * 2]     = __floats2bfloat162_rn(v.x, v.y);
    o[i * 2 + 1] = __floats2bfloat162_rn(v.z, v.w);
}

// 512 threads = 16 warps: w = wq(bit0) | wk(bit1) | wd(bits 2-3).
// Warp tile: 32 q-rows x 32 keys over dim-quarter wd (128 dims).
// wd=1..3 publish bf16x2-packed partials; wd=0 combines + tracks survivors.
extern "C" __global__ void __launch_bounds__(NTHR, 1)
attn_mma_kernel(const float* __restrict__ X, float* __restrict__ Y)
{
    extern __shared__ char smem[];
    const uint32_t sb = smem_u32(smem);
    const int tid  = threadIdx.x, lane = tid & 31, w = tid >> 5;
    const int wq = w & 1, wk = (w >> 1) & 1, wd = w >> 2;
    const int b  = blockIdx.x >> 6;
    const int q0 = (blockIdx.x & 63) * BQ;
    const __nv_bfloat16* Xb = g_Xb + (size_t)b * NSEQ * DIM;

    // stage Q (group0), preload K tile 0 (group1)
    load_tile(sb + SM_Q, Xb + (size_t)q0 * DIM, tid);
    load_tile(sb + SM_K(0), Xb, tid);

    // per-lane ldmatrix coordinates
    const int cd   = wd * 16;                                   // dim-quarter base (16B chunks)
    const int aco  = (lane >> 4);                               // +16B k-half for m2/m3
    const int bco  = (lane >> 3) & 1;
    const int arow0 = wq * 32 + (lane & 7) + ((lane >> 3) & 1) * 8;
    const int arow1 = arow0 + 16;
    const int brow0 = wk * 32 + (lane & 7) + ((lane >> 4) & 1) * 8;
    const int brow1 = brow0 + 16;
    const uint32_t abase0 = sb + SM_Q + arow0 * 1024;
    const uint32_t abase1 = sb + SM_Q + arow1 * 1024;

    float t1[4] = {-1e30f, -1e30f, -1e30f, -1e30f};
    float t2[4] = {-1e30f, -1e30f, -1e30f, -1e30f};
    int   i1[4] = {0, 0, 0, 0}, i2[4] = {0, 0, 0, 0};

    // red slot for this (wd,quad): 16 u32 x 32 lanes = 2KB
    const int quad = wq * 2 + wk;
    uint32_t* red_st = (uint32_t*)(smem + SM_RED) + ((wd - 1) * 4 + quad) * 512;  // wd>=1 only
    uint32_t* red_ld = (uint32_t*)(smem + SM_RED) + quad * 512;                    // base; +2048 u32 per src

    for (int kt = 0; kt < NKT; ++kt) {
        __syncthreads();                       // buffer (kt+1)&1 free; red consumed
        if (kt + 1 < NKT) {
            load_tile(sb + SM_K((kt + 1) & 1), Xb + (size_t)(kt + 1) * BK * DIM, tid);
            CP_WAIT(1);
        } else {
            CP_WAIT(0);
        }
        __syncthreads();                       // K(kt) (and Q on iter 0) visible

        const uint32_t kbase = sb + SM_K(kt & 1);
        float acc[2][4][4];
#pragma unroll
        for (int mt = 0; mt < 2; ++mt)
#pragma unroll
            for (int nt = 0; nt < 4; ++nt)
#pragma unroll
                for (int e = 0; e < 4; ++e) acc[mt][nt][e] = 0.0f;

#pragma unroll
        for (int ks = 0; ks < 8; ++ks) {        // 8 steps x 16 dims = this warp's 128 dims
            uint32_t A0[4], A1[4], B0[4], B1[4];
            ldsm4(A0, abase0 + swz(cd + ks * 2 + aco, arow0) * 16);
            ldsm4(A1, abase1 + swz(cd + ks * 2 + aco, arow1) * 16);
            ldsm4(B0, kbase + brow0 * 1024 + swz(cd + ks * 2 + bco, brow0) * 16);
            ldsm4(B1, kbase + brow1 * 1024 + swz(cd + ks * 2 + bco, brow1) * 16);
            mma16816(acc[0][0], A0, B0);
            mma16816(acc[0][1], A0, B0 + 2);
            mma16816(acc[0][2], A0, B1);
            mma16816(acc[0][3], A0, B1 + 2);
            mma16816(acc[1][0], A1, B0);
            mma16816(acc[1][1], A1, B0 + 2);
            mma16816(acc[1][2], A1, B1);
            mma16816(acc[1][3], A1, B1 + 2);
        }

        float* af = &acc[0][0][0];
        if (wd != 0) {                          // publish bf16x2-packed partials
#pragma unroll
            for (int j = 0; j < 16; ++j)
                red_st[j * 32 + lane] = pack_bf16x2(af[2 * j], af[2 * j + 1]);
        }
        __syncthreads();
        if (wd == 0) {
#pragma unroll
            for (int src = 0; src < 3; ++src) {
                const uint32_t* rs = red_ld + src * 2048;   // 4 quads x 512 u32 per src block
#pragma unroll
                for (int j = 0; j < 16; ++j) {
                    float2 p = unpack_bf16x2(rs[j * 32 + lane]);
                    af[2 * j]     += p.x;
                    af[2 * j + 1] += p.y;
                }
            }

            // fast-path: skip insertion if nothing can enter any of the 4 row-slots
            float tmax = af[0];
#pragma unroll
            for (int j = 1; j < 32; ++j) tmax = fmaxf(tmax, af[j]);
            const float tmin2 = fminf(fminf(t2[0], t2[1]), fminf(t2[2], t2[3]));
            if (tmax > tmin2) {
                const int cb = kt * BK + wk * 32 + (lane & 3) * 2;
#pragma unroll
                for (int mt = 0; mt < 2; ++mt)
#pragma unroll
                    for (int nt = 0; nt < 4; ++nt) {
                        const int r0 = mt * 2, r1 = mt * 2 + 1;
                        ins2(acc[mt][nt][0], cb + nt * 8,     t1[r0], i1[r0], t2[r0], i2[r0]);
                        ins2(acc[mt][nt][1], cb + nt * 8 + 1, t1[r0], i1[r0], t2[r0], i2[r0]);
                        ins2(acc[mt][nt][2], cb + nt * 8,     t1[r1], i1[r1], t2[r1], i2[r1]);
                        ins2(acc[mt][nt][3], cb + nt * 8 + 1, t1[r1], i1[r1], t2[r1], i2[r1]);
                    }
            }
        }
    }

    // publish per-thread candidates: cand[row][16] float2 (score, idx-bits)
    float2* cand = (float2*)(smem + SM_CAND);
    if (wd == 0) {
#pragma unroll
        for (int mt = 0; mt < 2; ++mt)
#pragma unroll
            for (int s = 0; s < 2; ++s) {
                const int row  = wq * 32 + mt * 16 + s * 8 + (lane >> 2);
                const int slot = (wk * 4 + (lane & 3)) * 2;
                const int rs   = mt * 2 + s;
                cand[row * 16 + slot]     = make_float2(t1[rs], __int_as_float(i1[rs]));
                cand[row * 16 + slot + 1] = make_float2(t2[rs], __int_as_float(i2[rs]));
            }
    }
    __syncthreads();

    // epilogue: one thread per query row; exact fp32 softmax over survivors.
    if (tid < BQ) {
        const int q = q0 + tid;
        float mx = -1e30f;
#pragma unroll
        for (int s = 0; s < 16; ++s) mx = fmaxf(mx, cand[tid * 16 + s].x);

        int idxs[16]; int n2 = 0;
#pragma unroll
        for (int s = 0; s < 16; ++s) {
            float2 c = cand[tid * 16 + s];
            if (c.x > mx - THRESH) idxs[n2++] = __float_as_int(c.y);
        }

        const float* Xf = X + (size_t)b * NSEQ * DIM;
        const float* xq = Xf + (size_t)q * DIM;
        float se[16], mex = -1e30f;
        for (int i = 0; i < n2; ++i) {
            const float* xj = Xf + (size_t)idxs[i] * DIM;
            float a0 = 0, a1 = 0, a2 = 0, a3 = 0;
            for (int d = 0; d < DIM; d += 4) {
                float4 a = *(const float4*)(xq + d), v = *(const float4*)(xj + d);
                a0 += a.x * v.x; a1 += a.y * v.y; a2 += a.z * v.z; a3 += a.w * v.w;
            }
            se[i] = (a0 + a1) + (a2 + a3);
            mex = fmaxf(mex, se[i]);
        }
        float wgt[16], denom = 0.0f;
        for (int i = 0; i < n2; ++i) { wgt[i] = expf(se[i] - mex); denom += wgt[i]; }
        const float inv = 1.0f / denom;

        float* y = Y + ((size_t)b * NSEQ + q) * DIM;
        for (int d = 0; d < DIM; d += 4) {
            float ax = 0, ay = 0, az = 0, aw = 0;
            for (int i = 0; i < n2; ++i) {
                float4 v = *(const float4*)(Xf + (size_t)idxs[i] * DIM + d);
                ax += wgt[i] * v.x; ay += wgt[i] * v.y; az += wgt[i] * v.z; aw += wgt[i] * v.w;
            }
            float4 o; o.x = ax * inv; o.y = ay * inv; o.z = az * inv; o.w = aw * inv;
            *(float4*)(y + d) = o;
        }
    }
}

extern "C" void kernel_launch(void* const* d_in, const int* in_sizes, int n_in,
                              void* d_out, int out_size)
{
    const float* X = (const float*)d_in[0];
    float*       Y = (float*)d_out;
    cudaFuncSetAttribute(attn_mma_kernel,
                         cudaFuncAttributeMaxDynamicSharedMemorySize, SMEM_BYTES);
    cvt_kernel<<<(NB * NSEQ * DIM) / (256 * 4), 256>>>(X);
    attn_mma_kernel<<<NB * (NSEQ / BQ), NTHR, SMEM_BYTES>>>(X, Y);
}

// round 12
// speedup vs baseline: 1.2097x; 1.2097x over previous
#include <cuda_runtime.h>
#include <cuda_bf16.h>
#include <cstdint>

#define NB    4
#define NSEQ  4096
#define DIM   512
#define BQ    64
#define BK    64
#define NKT   (NSEQ/BK)
#define NTHR  256
#define THRESH 70.0f

// bf16 copy of X (no cudaMalloc allowed -> device global scratch)
__device__ __nv_bfloat16 g_Xb[(size_t)NB*NSEQ*DIM];

// dynamic smem: 3-buffer K ring (rows 1024B, swizzled 16B chunks) + candidates
#define SM_K(i)  ((i)*65536)
#define SM_CAND  196608                 // float2[64][16] = 8KB
#define SMEM_BYTES (196608 + 8192)      // 204800

// ---------------- PTX helpers (plain-sm_103 legal) ----------------
__device__ __forceinline__ uint32_t smem_u32(const void* p) {
    uint32_t a;
    asm("{ .reg .u64 t; cvta.to.shared.u64 t, %1; cvt.u32.u64 %0, t; }" : "=r"(a) : "l"(p));
    return a;
}
#define CP16(dst, src) \
    asm volatile("cp.async.cg.shared.global [%0], [%1], 16;" \
        :: "r"((uint32_t)(dst)), "l"((unsigned long long)__cvta_generic_to_global((const void*)(src))) : "memory")
#define CP_COMMIT()  asm volatile("cp.async.commit_group;" ::: "memory")
#define CP_WAIT(n)   asm volatile("cp.async.wait_group %0;" :: "n"(n) : "memory")

__device__ __forceinline__ void ldsm4(uint32_t* r, uint32_t a) {
    asm volatile("ldmatrix.sync.aligned.m8n8.x4.shared.b16 {%0,%1,%2,%3}, [%4];"
        : "=r"(r[0]), "=r"(r[1]), "=r"(r[2]), "=r"(r[3]) : "r"(a));
}
__device__ __forceinline__ void mma16816(float* c, const uint32_t* a, const uint32_t* b) {
    asm volatile("mma.sync.aligned.m16n8k16.row.col.f32.bf16.bf16.f32 "
        "{%0,%1,%2,%3}, {%4,%5,%6,%7}, {%8,%9}, {%0,%1,%2,%3};"
        : "+f"(c[0]), "+f"(c[1]), "+f"(c[2]), "+f"(c[3])
        : "r"(a[0]), "r"(a[1]), "r"(a[2]), "r"(a[3]), "r"(b[0]), "r"(b[1]));
}
// in-row 16B-chunk swizzle: chunk c of row r lives at chunk ((c&~7)|((c^r)&7))
__device__ __forceinline__ int swz(int c, int r) { return (c & ~7) | ((c ^ r) & 7); }

__device__ __forceinline__ void ins2(float v, int idx, float& t1, int& i1, float& t2, int& i2) {
    if (v > t2) {
        if (v > t1) { t2 = t1; i2 = i1; t1 = v; i1 = idx; }
        else        { t2 = v;  i2 = idx; }
    }
}

// load a 64x512 bf16 tile (row-major, rows 1024B) into swizzled smem via cp.async
__device__ __forceinline__ void load_tile(uint32_t sbase, const __nv_bfloat16* src, int tid) {
#pragma unroll
    for (int i = 0; i < 16; ++i) {
        int c   = tid + i * NTHR;       // 4096 16B-chunks
        int row = c >> 6, ch = c & 63;
        CP16(sbase + row * 1024 + swz(ch, row) * 16, src + (size_t)row * DIM + ch * 8);
    }
    CP_COMMIT();
}

extern "C" __global__ void cvt_kernel(const float* __restrict__ X) {
    size_t i = (size_t)blockIdx.x * 256 + threadIdx.x;   // one float4 each
    float4 v = ((const float4*)X)[i];
    __nv_bfloat162* o = (__nv_bfloat162*)g_Xb;
    o[i * 2]     = __floats2bfloat162_rn(v.x, v.y);
    o[i * 2 + 1] = __floats2bfloat162_rn(v.z, v.w);
}

// 256 threads = 8 warps = 4 wq x 2 wk. Warp tile: 16 q-rows x 32 keys x 512 dims.
// Q fragments live in registers (loaded once); K streams through a 3-buffer ring.
extern "C" __global__ void __launch_bounds__(NTHR, 1)
attn_mma_kernel(const float* __restrict__ X, float* __restrict__ Y)
{
    extern __shared__ char smem[];
    const uint32_t sb = smem_u32(smem);
    const int tid  = threadIdx.x, lane = tid & 31, w = tid >> 5;
    const int wq = w & 3, wk = w >> 2;
    const int b  = blockIdx.x >> 6;
    const int q0 = (blockIdx.x & 63) * BQ;
    const __nv_bfloat16* Xb = g_Xb + (size_t)b * NSEQ * DIM;

    // prologue: stage Q into buf2, K0 into buf0, K1 into buf1
    load_tile(sb + SM_K(2), Xb + (size_t)q0 * DIM, tid);
    load_tile(sb + SM_K(0), Xb, tid);
    load_tile(sb + SM_K(1), Xb + (size_t)BK * DIM, tid);

    // per-lane ldmatrix coordinates
    const int aco  = (lane >> 4);                               // +16B k-half for m2/m3
    const int bco  = (lane >> 3) & 1;
    const int arow = wq * 16 + (lane & 7) + ((lane >> 3) & 1) * 8;
    const int brow0 = wk * 32 + (lane & 7) + ((lane >> 4) & 1) * 8;
    const int brow1 = brow0 + 16;

    // extract Q fragments into registers (128 regs): A[ks][4], ks = 16-dim step
    CP_WAIT(2);            // Q group retired (K0,K1 may be in flight)
    __syncthreads();
    uint32_t A[32][4];
    {
        const uint32_t qbase = sb + SM_K(2) + arow * 1024;
#pragma unroll
        for (int ks = 0; ks < 32; ++ks)
            ldsm4(A[ks], qbase + swz(ks * 2 + aco, arow) * 16);
    }
    __syncthreads();       // buf2 free for the ring

    float t1[2] = {-1e30f, -1e30f}, t2[2] = {-1e30f, -1e30f};
    int   i1[2] = {0, 0},           i2[2] = {0, 0};

    int bufk = 0;          // buf index of tile kt; ring 0,1,2,0,...
    for (int kt = 0; kt < NKT; ++kt) {
        if (kt + 1 < NKT) { CP_WAIT(1); } else { CP_WAIT(0); }  // tile kt landed
        __syncthreads();                                         // visible to all; compute(kt-1) done by all
        if (kt + 2 < NKT) {
            int ibuf = bufk + 2; if (ibuf >= 3) ibuf -= 3;
            load_tile(sb + SM_K(ibuf), Xb + (size_t)(kt + 2) * BK * DIM, tid);
        }

        const uint32_t kbase = sb + SM_K(bufk);
        const uint32_t kb0 = kbase + brow0 * 1024;
        const uint32_t kb1 = kbase + brow1 * 1024;
        float acc[4][4];
#pragma unroll
        for (int nt = 0; nt < 4; ++nt)
#pragma unroll
            for (int e = 0; e < 4; ++e) acc[nt][e] = 0.0f;

#pragma unroll
        for (int ks = 0; ks < 32; ++ks) {
            uint32_t B0[4], B1[4];
            ldsm4(B0, kb0 + swz(ks * 2 + bco, brow0) * 16);
            ldsm4(B1, kb1 + swz(ks * 2 + bco, brow1) * 16);
            mma16816(acc[0], A[ks], B0);
            mma16816(acc[1], A[ks], B0 + 2);
            mma16816(acc[2], A[ks], B1);
            mma16816(acc[3], A[ks], B1 + 2);
        }

        // survivor tracking (thread rows: wq*16 + lane/4, +8; cols: wk*32 + nt*8 + (lane&3)*2)
        float tmax = acc[0][0];
#pragma unroll
        for (int nt = 0; nt < 4; ++nt)
#pragma unroll
            for (int e = 0; e < 4; ++e) tmax = fmaxf(tmax, acc[nt][e]);
        if (tmax > fminf(t2[0], t2[1])) {
            const int cb = kt * BK + wk * 32 + (lane & 3) * 2;
#pragma unroll
            for (int nt = 0; nt < 4; ++nt) {
                ins2(acc[nt][0], cb + nt * 8,     t1[0], i1[0], t2[0], i2[0]);
                ins2(acc[nt][1], cb + nt * 8 + 1, t1[0], i1[0], t2[0], i2[0]);
                ins2(acc[nt][2], cb + nt * 8,     t1[1], i1[1], t2[1], i2[1]);
                ins2(acc[nt][3], cb + nt * 8 + 1, t1[1], i1[1], t2[1], i2[1]);
            }
        }

        if (++bufk == 3) bufk = 0;
    }

    // publish per-thread candidates: cand[row][16] float2 (score, idx-bits)
    float2* cand = (float2*)(smem + SM_CAND);
#pragma unroll
    for (int s = 0; s < 2; ++s) {
        const int row  = wq * 16 + s * 8 + (lane >> 2);
        const int slot = (wk * 4 + (lane & 3)) * 2;
        cand[row * 16 + slot]     = make_float2(t1[s], __int_as_float(i1[s]));
        cand[row * 16 + slot + 1] = make_float2(t2[s], __int_as_float(i2[s]));
    }
    __syncthreads();

    // epilogue: one thread per query row; exact fp32 softmax over survivors.
    if (tid < BQ) {
        const int q = q0 + tid;
        float mx = -1e30f;
#pragma unroll
        for (int s = 0; s < 16; ++s) mx = fmaxf(mx, cand[tid * 16 + s].x);

        int idxs[16]; int n2 = 0;
#pragma unroll
        for (int s = 0; s < 16; ++s) {
            float2 c = cand[tid * 16 + s];
            if (c.x > mx - THRESH) idxs[n2++] = __float_as_int(c.y);
        }

        const float* Xf = X + (size_t)b * NSEQ * DIM;
        const float* xq = Xf + (size_t)q * DIM;
        float se[16], mex = -1e30f;
        for (int i = 0; i < n2; ++i) {
            const float* xj = Xf + (size_t)idxs[i] * DIM;
            float a0 = 0, a1 = 0, a2 = 0, a3 = 0;
            for (int d = 0; d < DIM; d += 4) {
                float4 a = *(const float4*)(xq + d), v = *(const float4*)(xj + d);
                a0 += a.x * v.x; a1 += a.y * v.y; a2 += a.z * v.z; a3 += a.w * v.w;
            }
            se[i] = (a0 + a1) + (a2 + a3);
            mex = fmaxf(mex, se[i]);
        }
        float wgt[16], denom = 0.0f;
        for (int i = 0; i < n2; ++i) { wgt[i] = expf(se[i] - mex); denom += wgt[i]; }
        const float inv = 1.0f / denom;

        float* y = Y + ((size_t)b * NSEQ + q) * DIM;
        for (int d = 0; d < DIM; d += 4) {
            float ax = 0, ay = 0, az = 0, aw = 0;
            for (int i = 0; i < n2; ++i) {
                float4 v = *(const float4*)(Xf + (size_t)idxs[i] * DIM + d);
                ax += wgt[i] * v.x; ay += wgt[i] * v.y; az += wgt[i] * v.z; aw += wgt[i] * v.w;
            }
            float4 o; o.x = ax * inv; o.y = ay * inv; o.z = az * inv; o.w = aw * inv;
            *(float4*)(y + d) = o;
        }
    }
}

extern "C" void kernel_launch(void* const* d_in, const int* in_sizes, int n_in,
                              void* d_out, int out_size)
{
    const float* X = (const float*)d_in[0];
    float*       Y = (float*)d_out;
    cudaFuncSetAttribute(attn_mma_kernel,
                         cudaFuncAttributeMaxDynamicSharedMemorySize, SMEM_BYTES);
    cvt_kernel<<<(NB * NSEQ * DIM) / (256 * 4), 256>>>(X);
    attn_mma_kernel<<<NB * (NSEQ / BQ), NTHR, SMEM_BYTES>>>(X, Y);
}